// round 14
// baseline (speedup 1.0000x reference)
#include <cuda_runtime.h>
#include <cuda_fp16.h>
#include <cstdint>

#define EMBED 768
#define HEAD 64
#define SEQ 4096
#define BATCH 4

// Projections, fp16. g_Qh pre-scaled by 0.125*log2(e) (softmax in log2 domain).
// g_Qh/g_Kh: [B*T, 64] row-major. g_Vth: [B][64 head][4096 seq]
__device__ __half g_Qh[BATCH * SEQ * HEAD];
__device__ __half g_Kh[BATCH * SEQ * HEAD];
__device__ __half g_Vth[BATCH * HEAD * SEQ];

#define QSCALE 0.18033688f   // 0.125 * log2(e)

__device__ __forceinline__ uint32_t h2_to_u32(__half2 h) {
    union { __half2 h; uint32_t u; } cvt;
    cvt.h = h;
    return cvt.u;
}
__device__ __forceinline__ __half2 u32_to_h2(uint32_t u) {
    union { uint32_t u; __half2 h; } cvt;
    cvt.u = u;
    return cvt.h;
}
__device__ __forceinline__ float ex2(float x) {
    float r;
    asm("ex2.approx.ftz.f32 %0, %1;" : "=f"(r) : "f"(x));
    return r;
}

// tf32: D(16x8) += A(16x8) * B(8x8)
__device__ __forceinline__ void mma_tf32(float c[4],
    uint32_t a0, uint32_t a1, uint32_t a2, uint32_t a3,
    uint32_t b0, uint32_t b1)
{
    asm volatile(
        "mma.sync.aligned.m16n8k8.row.col.f32.tf32.tf32.f32 "
        "{%0,%1,%2,%3}, {%4,%5,%6,%7}, {%8,%9}, {%0,%1,%2,%3};"
        : "+f"(c[0]), "+f"(c[1]), "+f"(c[2]), "+f"(c[3])
        : "r"(a0), "r"(a1), "r"(a2), "r"(a3), "r"(b0), "r"(b1));
}

// fp16: D(16x8,f32) += A(16x16,f16) * B(16x8,f16)
__device__ __forceinline__ void mma_f16(float c[4],
    uint32_t a0, uint32_t a1, uint32_t a2, uint32_t a3,
    uint32_t b0, uint32_t b1)
{
    asm volatile(
        "mma.sync.aligned.m16n8k16.row.col.f32.f16.f16.f32 "
        "{%0,%1,%2,%3}, {%4,%5,%6,%7}, {%8,%9}, {%0,%1,%2,%3};"
        : "+f"(c[0]), "+f"(c[1]), "+f"(c[2]), "+f"(c[3])
        : "r"(a0), "r"(a1), "r"(a2), "r"(a3), "r"(b0), "r"(b1));
}

__device__ __forceinline__ uint32_t s2u(const void* p) {
    uint32_t a;
    asm("{ .reg .u64 t; cvta.to.shared.u64 t, %1; cvt.u32.u64 %0, t; }"
        : "=r"(a) : "l"(p));
    return a;
}

#define CPA16(dst, src) \
    asm volatile("cp.async.cg.shared.global [%0], [%1], 16;" :: "r"(dst), "l"(src) : "memory")
#define CPA_COMMIT() asm volatile("cp.async.commit_group;" ::: "memory")
#define CPA_WAIT1()  asm volatile("cp.async.wait_group 1;" ::: "memory")
#define CPA_WAIT0()  asm volatile("cp.async.wait_group 0;" ::: "memory")

// ---------------------------------------------------------------------------
// Fused QKV projection (unchanged from Round 13): 2(M) x 4(N) warp decomp,
// rna via +0x1000, double-buffered cp.async, single wave of 128 blocks.
// smem (floats): x0[0,8704) x1[8704,17408)
//                W(stage s, matrix m) at 17408 + s*13824 + m*4608  (64x72)
// ---------------------------------------------------------------------------
__global__ __launch_bounds__(256, 1) void qkv_fused_kernel(
    const float* __restrict__ x,
    const float* __restrict__ Wq, const float* __restrict__ bq,
    const float* __restrict__ Wk, const float* __restrict__ bk,
    const float* __restrict__ Wv, const float* __restrict__ bv)
{
    extern __shared__ __align__(16) float qsm[];
    const int XS = 8704, WBASE = 17408, WSTG = 13824, WMAT = 4608;

    const int t    = threadIdx.x;
    const int lane = t & 31;
    const int warp = t >> 5;
    const int mg   = warp >> 2;
    const int cg   = warp & 3;
    const int gid  = lane >> 2;
    const int l3   = lane & 3;
    const int row0 = blockIdx.x * 128;

    const uint32_t su = s2u(qsm);

#pragma unroll
    for (int st = 0; st < 2; st++) {
        int e0 = st * 64;
        uint32_t xbase = su + (st * XS) * 4;
        uint32_t wbase = su + (WBASE + st * WSTG) * 4;
#pragma unroll
        for (int i = 0; i < 8; i++) {
            int id = t + i * 256;
            int r  = id >> 4;
            int c  = (id & 15) << 2;
            CPA16(xbase + (r * 68 + c) * 4, &x[(size_t)(row0 + r) * EMBED + e0 + c]);
        }
#pragma unroll
        for (int i = 0; i < 12; i++) {
            int id = t + i * 256;
            int m  = id >> 10;
            int rm = id & 1023;
            int r  = rm >> 4;
            int c  = (rm & 15) << 2;
            const float* Wm = (m == 0) ? Wq : (m == 1) ? Wk : Wv;
            CPA16(wbase + (m * WMAT + r * 72 + c) * 4, &Wm[(size_t)(e0 + r) * HEAD + c]);
        }
        CPA_COMMIT();
    }

    float o[4][3][2][4];
#pragma unroll
    for (int mt = 0; mt < 4; mt++)
#pragma unroll
        for (int m = 0; m < 3; m++)
#pragma unroll
            for (int j = 0; j < 2; j++)
#pragma unroll
                for (int c = 0; c < 4; c++) o[mt][m][j][c] = 0.f;

    for (int chk = 0; chk < EMBED / 64; chk++) {
        CPA_WAIT1();
        __syncthreads();

        const int st = chk & 1;
        const uint32_t* sx = (const uint32_t*)(qsm + st * XS);
        const uint32_t* sw = (const uint32_t*)(qsm + WBASE + st * WSTG);

#pragma unroll
        for (int ks = 0; ks < 8; ks++) {
            int h = 8 * ks;
            uint32_t af[4][4];
#pragma unroll
            for (int mt = 0; mt < 4; mt++) {
                int row = 64 * mg + 16 * mt + gid;
                af[mt][0] = sx[(row) * 68 + h + l3] + 0x1000u;
                af[mt][1] = sx[(row + 8) * 68 + h + l3] + 0x1000u;
                af[mt][2] = sx[(row) * 68 + h + l3 + 4] + 0x1000u;
                af[mt][3] = sx[(row + 8) * 68 + h + l3 + 4] + 0x1000u;
            }
#pragma unroll
            for (int m = 0; m < 3; m++) {
                const uint32_t* swm = sw + m * WMAT;
#pragma unroll
                for (int j = 0; j < 2; j++) {
                    int n = 2 * cg + j;
                    uint32_t b0 = swm[(h + l3) * 72 + 8 * n + gid] + 0x1000u;
                    uint32_t b1 = swm[(h + l3 + 4) * 72 + 8 * n + gid] + 0x1000u;
#pragma unroll
                    for (int mt = 0; mt < 4; mt++)
                        mma_tf32(o[mt][m][j], af[mt][0], af[mt][1], af[mt][2], af[mt][3], b0, b1);
                }
            }
        }

        __syncthreads();

        if (chk + 2 < EMBED / 64) {
            int e0 = (chk + 2) * 64;
            uint32_t xbase = su + (st * XS) * 4;
            uint32_t wbase = su + (WBASE + st * WSTG) * 4;
#pragma unroll
            for (int i = 0; i < 8; i++) {
                int id = t + i * 256;
                int r  = id >> 4;
                int c  = (id & 15) << 2;
                CPA16(xbase + (r * 68 + c) * 4, &x[(size_t)(row0 + r) * EMBED + e0 + c]);
            }
#pragma unroll
            for (int i = 0; i < 12; i++) {
                int id = t + i * 256;
                int m  = id >> 10;
                int rm = id & 1023;
                int r  = rm >> 4;
                int c  = (rm & 15) << 2;
                const float* Wm = (m == 0) ? Wq : (m == 1) ? Wk : Wv;
                CPA16(wbase + (m * WMAT + r * 72 + c) * 4, &Wm[(size_t)(e0 + r) * HEAD + c]);
            }
        }
        CPA_COMMIT();
    }
    CPA_WAIT0();

    const int bb   = (row0) / SEQ;
    __half* vt = g_Vth + (size_t)bb * HEAD * SEQ;

#pragma unroll
    for (int mt = 0; mt < 4; mt++) {
        const int rowA = row0 + 64 * mg + 16 * mt + gid;
        const int rowB = rowA + 8;
        const int seqA = rowA - bb * SEQ;
#pragma unroll
        for (int j = 0; j < 2; j++) {
            int n  = 2 * cg + j;
            int cb = 8 * n + 2 * l3;
            {
                float b0 = bq[cb], b1 = bq[cb + 1];
                *(__half2*)&g_Qh[(size_t)rowA * HEAD + cb] =
                    __floats2half2_rn((o[mt][0][j][0] + b0) * QSCALE,
                                      (o[mt][0][j][1] + b1) * QSCALE);
                *(__half2*)&g_Qh[(size_t)rowB * HEAD + cb] =
                    __floats2half2_rn((o[mt][0][j][2] + b0) * QSCALE,
                                      (o[mt][0][j][3] + b1) * QSCALE);
            }
            {
                float b0 = bk[cb], b1 = bk[cb + 1];
                *(__half2*)&g_Kh[(size_t)rowA * HEAD + cb] =
                    __floats2half2_rn(o[mt][1][j][0] + b0, o[mt][1][j][1] + b1);
                *(__half2*)&g_Kh[(size_t)rowB * HEAD + cb] =
                    __floats2half2_rn(o[mt][1][j][2] + b0, o[mt][1][j][3] + b1);
            }
            {
                float b0 = bv[cb], b1 = bv[cb + 1];
                vt[(size_t)(cb)     * SEQ + seqA]     = __float2half_rn(o[mt][2][j][0] + b0);
                vt[(size_t)(cb + 1) * SEQ + seqA]     = __float2half_rn(o[mt][2][j][1] + b1);
                vt[(size_t)(cb)     * SEQ + seqA + 8] = __float2half_rn(o[mt][2][j][2] + b0);
                vt[(size_t)(cb + 1) * SEQ + seqA + 8] = __float2half_rn(o[mt][2][j][3] + b1);
            }
        }
    }
}

// ---------------------------------------------------------------------------
// Flash attention: causal, fp16 m16n8k16, split-kn, LPT-balanced.
// SOFTWARE-PIPELINED: S(kt+1) MMAs issued in iter kt (after softmax/pack of
// S(kt)), so the softmax chain of kt+1 overlaps the S'(kt+1)+PV(kt) MMA burst
// + prefetch + barrier. 4-stage K/V ring, prefetch distance 3: the tail
// wait_group(1)+barrier of iter kt makes tiles <= kt+2 block-visible, so the
// mid-iter S'(kt+2) next round needs no extra sync.
// smem bytes: Q[0,9216) K stage s at 9216+9216s (s<4), V at 46080+9216s.
// Total 82944 B -> 2 blocks/SM.
// ---------------------------------------------------------------------------
__global__ __launch_bounds__(256, 2) void flash_kernel(float* __restrict__ out)
{
    extern __shared__ __align__(16) unsigned char smraw[];
    __half* sh = (__half*)smraw;
    __half* sQ = sh;                     // 64 x 72 halves

    const int bid = blockIdx.x;
    const int rr  = (bid < 148) ? bid : 403 - bid;
    const int qt  = 63 - (rr >> 2);
    const int b   = rr & 3;

    const int t    = threadIdx.x;
    const int lane = t & 31;
    const int warp = t >> 5;
    const int g    = warp >> 2;          // column-group 0/1
    const int w16  = (warp & 3) << 4;
    const int gid  = lane >> 2;
    const int l3   = lane & 3;
    const int r0   = w16 + gid;
    const int l2   = 2 * l3;

    const __half* __restrict__ Qg = g_Qh + (size_t)b * SEQ * HEAD;
    const __half* __restrict__ Kg = g_Kh + (size_t)b * SEQ * HEAD;
    const __half* __restrict__ Vg = g_Vth + (size_t)b * HEAD * SEQ;

    const uint32_t su = s2u(sh);

    // g0: Q + K0 + V0
#pragma unroll
    for (int i = 0; i < 2; i++) {
        int id = t + i * 256;
        int r  = id >> 3;
        int ch = id & 7;
        CPA16(su + r * 144 + 16 * ch, Qg + (size_t)(qt * 64 + r) * HEAD + 8 * ch);
        CPA16(su + 9216 + r * 144 + 16 * ch, Kg + (size_t)r * HEAD + 8 * ch);
        CPA16(su + 46080 + r * 144 + 16 * ch, Vg + (size_t)r * SEQ + 8 * ch);
    }
    CPA_COMMIT();
    // g1: K1 + V1 ; g2: K2 + V2  (tiles 1,2 always in-bounds: SEQ/64 = 64)
#pragma unroll
    for (int sgl = 1; sgl <= 2; sgl++) {
#pragma unroll
        for (int i = 0; i < 2; i++) {
            int id = t + i * 256;
            int r  = id >> 3;
            int ch = id & 7;
            CPA16(su + 9216 + sgl * 9216 + r * 144 + 16 * ch,
                  Kg + (size_t)(sgl * 64 + r) * HEAD + 8 * ch);
            CPA16(su + 46080 + sgl * 9216 + r * 144 + 16 * ch,
                  Vg + (size_t)r * SEQ + sgl * 64 + 8 * ch);
        }
        CPA_COMMIT();
    }

    CPA_WAIT1();            // g0,g1 done -> tiles 0,1 landed (this thread)
    __syncthreads();        // ... and visible block-wide
    uint32_t qf[4][4];
#pragma unroll
    for (int ks = 0; ks < 4; ks++) {
        int k0 = 16 * ks;
        qf[ks][0] = *(const uint32_t*)&sQ[(r0) * 72 + k0 + l2];
        qf[ks][1] = *(const uint32_t*)&sQ[(r0 + 8) * 72 + k0 + l2];
        qf[ks][2] = *(const uint32_t*)&sQ[(r0) * 72 + k0 + l2 + 8];
        qf[ks][3] = *(const uint32_t*)&sQ[(r0 + 8) * 72 + k0 + l2 + 8];
    }

    float m0 = -1e30f, m1 = -1e30f, l0 = 0.f, l1 = 0.f;
    float o[8][4];
#pragma unroll
    for (int n = 0; n < 8; n++)
#pragma unroll
        for (int c = 0; c < 4; c++) o[n][c] = 0.f;

    // ---- S(0) ----
    float s[4][4];
#pragma unroll
    for (int n = 0; n < 4; n++)
#pragma unroll
        for (int c = 0; c < 4; c++) s[n][c] = 0.f;
    {
        const __half* sK0 = sh + 4608;
#pragma unroll
        for (int ks = 0; ks < 4; ks++) {
            int k0 = 16 * ks;
#pragma unroll
            for (int n = 0; n < 4; n++) {
                int kr = 32 * g + 8 * n + gid;
                uint32_t b0 = *(const uint32_t*)&sK0[kr * 72 + k0 + l2];
                uint32_t b1 = *(const uint32_t*)&sK0[kr * 72 + k0 + l2 + 8];
                mma_f16(s[n], qf[ks][0], qf[ks][1], qf[ks][2], qf[ks][3], b0, b1);
            }
        }
    }

    int st = 0;              // ring slot of current kt
    for (int kt = 0; kt <= qt; kt++) {
        // s == S(kt), unmasked. Mask (diagonal tile only); Q carries the scale.
        if (kt == qt) {
#pragma unroll
            for (int n = 0; n < 4; n++) {
                int c0 = 32 * g + 8 * n + l2;
                if (c0     > r0    ) s[n][0] = -1e30f;
                if (c0 + 1 > r0    ) s[n][1] = -1e30f;
                if (c0     > r0 + 8) s[n][2] = -1e30f;
                if (c0 + 1 > r0 + 8) s[n][3] = -1e30f;
            }
        }

        float mx0 = fmaxf(fmaxf(s[0][0], s[0][1]), fmaxf(s[1][0], s[1][1]));
        mx0 = fmaxf(mx0, fmaxf(fmaxf(s[2][0], s[2][1]), fmaxf(s[3][0], s[3][1])));
        float mx1 = fmaxf(fmaxf(s[0][2], s[0][3]), fmaxf(s[1][2], s[1][3]));
        mx1 = fmaxf(mx1, fmaxf(fmaxf(s[2][2], s[2][3]), fmaxf(s[3][2], s[3][3])));

        __half2 hmx = __floats2half2_rn(mx0, mx1);
        hmx = __hmax2(hmx, u32_to_h2(__shfl_xor_sync(0xffffffffu, h2_to_u32(hmx), 1)));
        hmx = __hmax2(hmx, u32_to_h2(__shfl_xor_sync(0xffffffffu, h2_to_u32(hmx), 2)));
        float2 fmx = __half22float2(hmx);

        float mn0 = fmaxf(m0, fmx.x);
        float mn1 = fmaxf(m1, fmx.y);
        float alpha0 = ex2(m0 - mn0);
        float alpha1 = ex2(m1 - mn1);
        m0 = mn0; m1 = mn1;

        float rs0 = 0.f, rs1 = 0.f;
#pragma unroll
        for (int n = 0; n < 4; n++) {
            s[n][0] = ex2(s[n][0] - mn0);
            s[n][1] = ex2(s[n][1] - mn0);
            s[n][2] = ex2(s[n][2] - mn1);
            s[n][3] = ex2(s[n][3] - mn1);
            rs0 += s[n][0] + s[n][1];
            rs1 += s[n][2] + s[n][3];
        }
        l0 = l0 * alpha0 + rs0;
        l1 = l1 * alpha1 + rs1;

#pragma unroll
        for (int n = 0; n < 8; n++) {
            o[n][0] *= alpha0; o[n][1] *= alpha0;
            o[n][2] *= alpha1; o[n][3] *= alpha1;
        }

        // Pack P (frees s for the pipelined S')
        uint32_t p[8];
#pragma unroll
        for (int n = 0; n < 4; n++) {
            p[2 * n]     = h2_to_u32(__floats2half2_rn(s[n][0], s[n][1]));
            p[2 * n + 1] = h2_to_u32(__floats2half2_rn(s[n][2], s[n][3]));
        }

        // ---- S(kt+1) into s (tile kt+1 is block-visible) ----
        if (kt < qt) {
            int ns = st + 1; if (ns == 4) ns = 0;
            const __half* sKn = sh + 4608 + ns * 4608;
#pragma unroll
            for (int n = 0; n < 4; n++)
#pragma unroll
                for (int c = 0; c < 4; c++) s[n][c] = 0.f;
#pragma unroll
            for (int ks = 0; ks < 4; ks++) {
                int k0 = 16 * ks;
#pragma unroll
                for (int n = 0; n < 4; n++) {
                    int kr = 32 * g + 8 * n + gid;
                    uint32_t b0 = *(const uint32_t*)&sKn[kr * 72 + k0 + l2];
                    uint32_t b1 = *(const uint32_t*)&sKn[kr * 72 + k0 + l2 + 8];
                    mma_f16(s[n], qf[ks][0], qf[ks][1], qf[ks][2], qf[ks][3], b0, b1);
                }
            }
        }

        // ---- PV(kt) ----
        {
            const __half* sVc = sh + 23040 + st * 4608;
#pragma unroll
            for (int ks = 0; ks < 2; ks++) {
                uint32_t a0 = p[4 * ks + 0];
                uint32_t a1 = p[4 * ks + 1];
                uint32_t a2 = p[4 * ks + 2];
                uint32_t a3 = p[4 * ks + 3];
                int kb = 32 * g + 16 * ks + l2;
#pragma unroll
                for (int n = 0; n < 8; n++) {
                    int vr = 8 * n + gid;
                    uint32_t b0 = *(const uint32_t*)&sVc[vr * 72 + kb];
                    uint32_t b1 = *(const uint32_t*)&sVc[vr * 72 + kb + 8];
                    mma_f16(o[n], a0, a1, a2, a3, b0, b1);
                }
            }
        }

        // Prefetch tile kt+3 into slot (st+3)%4 (its K read in iter kt-2,
        // V in iter kt-1; both sealed by the end-of-(kt-1) barrier).
        if (kt + 3 <= qt) {
            int ps = st + 3; if (ps >= 4) ps -= 4;
#pragma unroll
            for (int i = 0; i < 2; i++) {
                int id = t + i * 256;
                int r  = id >> 3;
                int ch = id & 7;
                CPA16(su + 9216 + ps * 9216 + r * 144 + 16 * ch,
                      Kg + (size_t)((kt + 3) * 64 + r) * HEAD + 8 * ch);
                CPA16(su + 46080 + ps * 9216 + r * 144 + 16 * ch,
                      Vg + (size_t)r * SEQ + (kt + 3) * 64 + 8 * ch);
            }
        }
        CPA_COMMIT();
        CPA_WAIT1();         // tile kt+2 landed (this thread)
        __syncthreads();     // ... visible block-wide; slots sealed for reuse
        if (++st == 4) st = 0;
    }

    CPA_WAIT0();
    __syncthreads();

    l0 += __shfl_xor_sync(0xffffffffu, l0, 1);
    l0 += __shfl_xor_sync(0xffffffffu, l0, 2);
    l1 += __shfl_xor_sync(0xffffffffu, l1, 1);
    l1 += __shfl_xor_sync(0xffffffffu, l1, 2);

    float* sML = (float*)smraw;
    if (l3 == 0) {
        sML[((g * 64 + r0)     << 1) + 0] = m0;
        sML[((g * 64 + r0)     << 1) + 1] = l0;
        sML[((g * 64 + r0 + 8) << 1) + 0] = m1;
        sML[((g * 64 + r0 + 8) << 1) + 1] = l1;
    }
    __syncthreads();
    const int og = 1 - g;
    float mo0 = sML[((og * 64 + r0)     << 1) + 0];
    float lo0 = sML[((og * 64 + r0)     << 1) + 1];
    float mo1 = sML[((og * 64 + r0 + 8) << 1) + 0];
    float lo1 = sML[((og * 64 + r0 + 8) << 1) + 1];

    float M0 = fmaxf(m0, mo0), M1 = fmaxf(m1, mo1);
    float sc0 = ex2(m0 - M0), sc1 = ex2(m1 - M1);
    float L0 = l0 * sc0 + lo0 * ex2(mo0 - M0);
    float L1 = l1 * sc1 + lo1 * ex2(mo1 - M1);

#pragma unroll
    for (int n = 0; n < 8; n++) {
        o[n][0] *= sc0; o[n][1] *= sc0;
        o[n][2] *= sc1; o[n][3] *= sc1;
    }

    float* sOB = (float*)(smraw + 9216);
    if (g == 1) {
#pragma unroll
        for (int n = 0; n < 8; n++) {
            int cb = 8 * n + l2;
            sOB[(r0) * 68 + cb + 0]     = o[n][0];
            sOB[(r0) * 68 + cb + 1]     = o[n][1];
            sOB[(r0 + 8) * 68 + cb + 0] = o[n][2];
            sOB[(r0 + 8) * 68 + cb + 1] = o[n][3];
        }
    }
    __syncthreads();
    if (g == 0) {
        float inv0 = 1.f / L0;
        float inv1 = 1.f / L1;
        size_t orow0 = (size_t)b * SEQ + qt * 64 + r0;
#pragma unroll
        for (int n = 0; n < 8; n++) {
            int cb = 8 * n + l2;
            float2 v0, v1;
            v0.x = (o[n][0] + sOB[(r0) * 68 + cb + 0])     * inv0;
            v0.y = (o[n][1] + sOB[(r0) * 68 + cb + 1])     * inv0;
            v1.x = (o[n][2] + sOB[(r0 + 8) * 68 + cb + 0]) * inv1;
            v1.y = (o[n][3] + sOB[(r0 + 8) * 68 + cb + 1]) * inv1;
            *(float2*)&out[orow0 * HEAD + cb]       = v0;
            *(float2*)&out[(orow0 + 8) * HEAD + cb] = v1;
        }
    }
}

extern "C" void kernel_launch(void* const* d_in, const int* in_sizes, int n_in,
                              void* d_out, int out_size)
{
    const float* x  = (const float*)d_in[0];
    const float* Wq = (const float*)d_in[1];
    const float* bq = (const float*)d_in[2];
    const float* Wk = (const float*)d_in[3];
    const float* bk = (const float*)d_in[4];
    const float* Wv = (const float*)d_in[5];
    const float* bv = (const float*)d_in[6];
    float* out = (float*)d_out;

    const size_t QKV_SMEM = (size_t)45056 * sizeof(float);   // 180224 B
    cudaFuncSetAttribute(qkv_fused_kernel, cudaFuncAttributeMaxDynamicSharedMemorySize,
                         (int)QKV_SMEM);
    qkv_fused_kernel<<<SEQ * BATCH / 128, 256, QKV_SMEM>>>(x, Wq, bq, Wk, bk, Wv, bv);

    const size_t FLASH_SMEM = 82944;     // bytes: Q 9216 + K 4x9216 + Vt 4x9216
    cudaFuncSetAttribute(flash_kernel, cudaFuncAttributeMaxDynamicSharedMemorySize,
                         (int)FLASH_SMEM);
    flash_kernel<<<SEQ / 64 * BATCH, 256, FLASH_SMEM>>>(out);
}

// round 15
// speedup vs baseline: 1.0422x; 1.0422x over previous
#include <cuda_runtime.h>
#include <cuda_fp16.h>
#include <cstdint>

#define EMBED 768
#define HEAD 64
#define SEQ 4096
#define BATCH 4

// Projections, fp16. g_Qh pre-scaled by 0.125*log2(e) (softmax in log2 domain).
// g_Qh/g_Kh: [B*T, 64] row-major. g_Vth: [B][64 head][4096 seq]
__device__ __half g_Qh[BATCH * SEQ * HEAD];
__device__ __half g_Kh[BATCH * SEQ * HEAD];
__device__ __half g_Vth[BATCH * HEAD * SEQ];

#define QSCALE 0.18033688f   // 0.125 * log2(e)
#define ONES_H2 0x3C003C00u  // half2(1.0, 1.0)

__device__ __forceinline__ uint32_t h2_to_u32(__half2 h) {
    union { __half2 h; uint32_t u; } cvt;
    cvt.h = h;
    return cvt.u;
}
__device__ __forceinline__ __half2 u32_to_h2(uint32_t u) {
    union { uint32_t u; __half2 h; } cvt;
    cvt.u = u;
    return cvt.h;
}
__device__ __forceinline__ float ex2(float x) {
    float r;
    asm("ex2.approx.ftz.f32 %0, %1;" : "=f"(r) : "f"(x));
    return r;
}
// two fp16 ex2 in one MUFU op; input/output packed half2
__device__ __forceinline__ uint32_t ex2_h2(uint32_t x) {
    uint32_t r;
    asm("ex2.approx.f16x2 %0, %1;" : "=r"(r) : "r"(x));
    return r;
}

// tf32: D(16x8) += A(16x8) * B(8x8)
__device__ __forceinline__ void mma_tf32(float c[4],
    uint32_t a0, uint32_t a1, uint32_t a2, uint32_t a3,
    uint32_t b0, uint32_t b1)
{
    asm volatile(
        "mma.sync.aligned.m16n8k8.row.col.f32.tf32.tf32.f32 "
        "{%0,%1,%2,%3}, {%4,%5,%6,%7}, {%8,%9}, {%0,%1,%2,%3};"
        : "+f"(c[0]), "+f"(c[1]), "+f"(c[2]), "+f"(c[3])
        : "r"(a0), "r"(a1), "r"(a2), "r"(a3), "r"(b0), "r"(b1));
}

// fp16: D(16x8,f32) += A(16x16,f16) * B(16x8,f16)
__device__ __forceinline__ void mma_f16(float c[4],
    uint32_t a0, uint32_t a1, uint32_t a2, uint32_t a3,
    uint32_t b0, uint32_t b1)
{
    asm volatile(
        "mma.sync.aligned.m16n8k16.row.col.f32.f16.f16.f32 "
        "{%0,%1,%2,%3}, {%4,%5,%6,%7}, {%8,%9}, {%0,%1,%2,%3};"
        : "+f"(c[0]), "+f"(c[1]), "+f"(c[2]), "+f"(c[3])
        : "r"(a0), "r"(a1), "r"(a2), "r"(a3), "r"(b0), "r"(b1));
}

__device__ __forceinline__ uint32_t s2u(const void* p) {
    uint32_t a;
    asm("{ .reg .u64 t; cvta.to.shared.u64 t, %1; cvt.u32.u64 %0, t; }"
        : "=r"(a) : "l"(p));
    return a;
}

#define CPA16(dst, src) \
    asm volatile("cp.async.cg.shared.global [%0], [%1], 16;" :: "r"(dst), "l"(src) : "memory")
#define CPA_COMMIT() asm volatile("cp.async.commit_group;" ::: "memory")
#define CPA_WAIT1()  asm volatile("cp.async.wait_group 1;" ::: "memory")
#define CPA_WAIT0()  asm volatile("cp.async.wait_group 0;" ::: "memory")

// ---------------------------------------------------------------------------
// Fused QKV projection (unchanged, Round-13 proven): 2(M) x 4(N) warp decomp,
// rna via +0x1000, double-buffered cp.async, single wave of 128 blocks.
// smem (floats): x0[0,8704) x1[8704,17408)
//                W(stage s, matrix m) at 17408 + s*13824 + m*4608  (64x72)
// ---------------------------------------------------------------------------
__global__ __launch_bounds__(256, 1) void qkv_fused_kernel(
    const float* __restrict__ x,
    const float* __restrict__ Wq, const float* __restrict__ bq,
    const float* __restrict__ Wk, const float* __restrict__ bk,
    const float* __restrict__ Wv, const float* __restrict__ bv)
{
    extern __shared__ __align__(16) float qsm[];
    const int XS = 8704, WBASE = 17408, WSTG = 13824, WMAT = 4608;

    const int t    = threadIdx.x;
    const int lane = t & 31;
    const int warp = t >> 5;
    const int mg   = warp >> 2;
    const int cg   = warp & 3;
    const int gid  = lane >> 2;
    const int l3   = lane & 3;
    const int row0 = blockIdx.x * 128;

    const uint32_t su = s2u(qsm);

#pragma unroll
    for (int st = 0; st < 2; st++) {
        int e0 = st * 64;
        uint32_t xbase = su + (st * XS) * 4;
        uint32_t wbase = su + (WBASE + st * WSTG) * 4;
#pragma unroll
        for (int i = 0; i < 8; i++) {
            int id = t + i * 256;
            int r  = id >> 4;
            int c  = (id & 15) << 2;
            CPA16(xbase + (r * 68 + c) * 4, &x[(size_t)(row0 + r) * EMBED + e0 + c]);
        }
#pragma unroll
        for (int i = 0; i < 12; i++) {
            int id = t + i * 256;
            int m  = id >> 10;
            int rm = id & 1023;
            int r  = rm >> 4;
            int c  = (rm & 15) << 2;
            const float* Wm = (m == 0) ? Wq : (m == 1) ? Wk : Wv;
            CPA16(wbase + (m * WMAT + r * 72 + c) * 4, &Wm[(size_t)(e0 + r) * HEAD + c]);
        }
        CPA_COMMIT();
    }

    float o[4][3][2][4];
#pragma unroll
    for (int mt = 0; mt < 4; mt++)
#pragma unroll
        for (int m = 0; m < 3; m++)
#pragma unroll
            for (int j = 0; j < 2; j++)
#pragma unroll
                for (int c = 0; c < 4; c++) o[mt][m][j][c] = 0.f;

    for (int chk = 0; chk < EMBED / 64; chk++) {
        CPA_WAIT1();
        __syncthreads();

        const int st = chk & 1;
        const uint32_t* sx = (const uint32_t*)(qsm + st * XS);
        const uint32_t* sw = (const uint32_t*)(qsm + WBASE + st * WSTG);

#pragma unroll
        for (int ks = 0; ks < 8; ks++) {
            int h = 8 * ks;
            uint32_t af[4][4];
#pragma unroll
            for (int mt = 0; mt < 4; mt++) {
                int row = 64 * mg + 16 * mt + gid;
                af[mt][0] = sx[(row) * 68 + h + l3] + 0x1000u;
                af[mt][1] = sx[(row + 8) * 68 + h + l3] + 0x1000u;
                af[mt][2] = sx[(row) * 68 + h + l3 + 4] + 0x1000u;
                af[mt][3] = sx[(row + 8) * 68 + h + l3 + 4] + 0x1000u;
            }
#pragma unroll
            for (int m = 0; m < 3; m++) {
                const uint32_t* swm = sw + m * WMAT;
#pragma unroll
                for (int j = 0; j < 2; j++) {
                    int n = 2 * cg + j;
                    uint32_t b0 = swm[(h + l3) * 72 + 8 * n + gid] + 0x1000u;
                    uint32_t b1 = swm[(h + l3 + 4) * 72 + 8 * n + gid] + 0x1000u;
#pragma unroll
                    for (int mt = 0; mt < 4; mt++)
                        mma_tf32(o[mt][m][j], af[mt][0], af[mt][1], af[mt][2], af[mt][3], b0, b1);
                }
            }
        }

        __syncthreads();

        if (chk + 2 < EMBED / 64) {
            int e0 = (chk + 2) * 64;
            uint32_t xbase = su + (st * XS) * 4;
            uint32_t wbase = su + (WBASE + st * WSTG) * 4;
#pragma unroll
            for (int i = 0; i < 8; i++) {
                int id = t + i * 256;
                int r  = id >> 4;
                int c  = (id & 15) << 2;
                CPA16(xbase + (r * 68 + c) * 4, &x[(size_t)(row0 + r) * EMBED + e0 + c]);
            }
#pragma unroll
            for (int i = 0; i < 12; i++) {
                int id = t + i * 256;
                int m  = id >> 10;
                int rm = id & 1023;
                int r  = rm >> 4;
                int c  = (rm & 15) << 2;
                const float* Wm = (m == 0) ? Wq : (m == 1) ? Wk : Wv;
                CPA16(wbase + (m * WMAT + r * 72 + c) * 4, &Wm[(size_t)(e0 + r) * HEAD + c]);
            }
        }
        CPA_COMMIT();
    }
    CPA_WAIT0();

    const int bb   = (row0) / SEQ;
    __half* vt = g_Vth + (size_t)bb * HEAD * SEQ;

#pragma unroll
    for (int mt = 0; mt < 4; mt++) {
        const int rowA = row0 + 64 * mg + 16 * mt + gid;
        const int rowB = rowA + 8;
        const int seqA = rowA - bb * SEQ;
#pragma unroll
        for (int j = 0; j < 2; j++) {
            int n  = 2 * cg + j;
            int cb = 8 * n + 2 * l3;
            {
                float b0 = bq[cb], b1 = bq[cb + 1];
                *(__half2*)&g_Qh[(size_t)rowA * HEAD + cb] =
                    __floats2half2_rn((o[mt][0][j][0] + b0) * QSCALE,
                                      (o[mt][0][j][1] + b1) * QSCALE);
                *(__half2*)&g_Qh[(size_t)rowB * HEAD + cb] =
                    __floats2half2_rn((o[mt][0][j][2] + b0) * QSCALE,
                                      (o[mt][0][j][3] + b1) * QSCALE);
            }
            {
                float b0 = bk[cb], b1 = bk[cb + 1];
                *(__half2*)&g_Kh[(size_t)rowA * HEAD + cb] =
                    __floats2half2_rn(o[mt][1][j][0] + b0, o[mt][1][j][1] + b1);
                *(__half2*)&g_Kh[(size_t)rowB * HEAD + cb] =
                    __floats2half2_rn(o[mt][1][j][2] + b0, o[mt][1][j][3] + b1);
            }
            {
                float b0 = bv[cb], b1 = bv[cb + 1];
                vt[(size_t)(cb)     * SEQ + seqA]     = __float2half_rn(o[mt][2][j][0] + b0);
                vt[(size_t)(cb + 1) * SEQ + seqA]     = __float2half_rn(o[mt][2][j][1] + b1);
                vt[(size_t)(cb)     * SEQ + seqA + 8] = __float2half_rn(o[mt][2][j][2] + b0);
                vt[(size_t)(cb + 1) * SEQ + seqA + 8] = __float2half_rn(o[mt][2][j][3] + b1);
            }
        }
    }
}

// ---------------------------------------------------------------------------
// Flash attention (Round-13 mainloop structure + two softmax diet tricks):
// - l accumulated by a virtual 9th PV n-tile with constant-ones B operand
//   (o[8]): deletes rs FADDs, l updates, and the final l shfl-reduce.
// - P computed by ex2.approx.f16x2 on packed (s - mn): halves MUFU ops and
//   produces packed fp16 P directly.
// 3-stage K/V ring, prefetch distance 2, one __syncthreads per iter.
// Softmax in log2 domain (Q pre-scaled). LPT-balanced tiles.
// smem bytes: Q[0,9216) K stage s at 9216+9216s (s<3), V at 36864+9216s.
// Total 64512 B -> 2 blocks/SM.
// ---------------------------------------------------------------------------
__global__ __launch_bounds__(256, 2) void flash_kernel(float* __restrict__ out)
{
    extern __shared__ __align__(16) unsigned char smraw[];
    __half* sh = (__half*)smraw;
    __half* sQ = sh;                     // 64 x 72 halves

    const int bid = blockIdx.x;
    const int rr  = (bid < 148) ? bid : 403 - bid;
    const int qt  = 63 - (rr >> 2);
    const int b   = rr & 3;

    const int t    = threadIdx.x;
    const int lane = t & 31;
    const int warp = t >> 5;
    const int g    = warp >> 2;          // column-group 0/1
    const int w16  = (warp & 3) << 4;
    const int gid  = lane >> 2;
    const int l3   = lane & 3;
    const int r0   = w16 + gid;
    const int l2   = 2 * l3;

    const __half* __restrict__ Qg = g_Qh + (size_t)b * SEQ * HEAD;
    const __half* __restrict__ Kg = g_Kh + (size_t)b * SEQ * HEAD;
    const __half* __restrict__ Vg = g_Vth + (size_t)b * HEAD * SEQ;

    const uint32_t su = s2u(sh);

    // g0: Q + K0 + V0
#pragma unroll
    for (int i = 0; i < 2; i++) {
        int id = t + i * 256;
        int r  = id >> 3;
        int ch = id & 7;
        CPA16(su + r * 144 + 16 * ch, Qg + (size_t)(qt * 64 + r) * HEAD + 8 * ch);
        CPA16(su + 9216 + r * 144 + 16 * ch, Kg + (size_t)r * HEAD + 8 * ch);
        CPA16(su + 36864 + r * 144 + 16 * ch, Vg + (size_t)r * SEQ + 8 * ch);
    }
    CPA_COMMIT();
    // g1: K1 + V1
#pragma unroll
    for (int i = 0; i < 2; i++) {
        int id = t + i * 256;
        int r  = id >> 3;
        int ch = id & 7;
        CPA16(su + 9216 + 9216 + r * 144 + 16 * ch,
              Kg + (size_t)(64 + r) * HEAD + 8 * ch);
        CPA16(su + 36864 + 9216 + r * 144 + 16 * ch,
              Vg + (size_t)r * SEQ + 64 + 8 * ch);
    }
    CPA_COMMIT();

    CPA_WAIT1();            // g0 (Q + stage0) landed
    __syncthreads();
    uint32_t qf[4][4];
#pragma unroll
    for (int ks = 0; ks < 4; ks++) {
        int k0 = 16 * ks;
        qf[ks][0] = *(const uint32_t*)&sQ[(r0) * 72 + k0 + l2];
        qf[ks][1] = *(const uint32_t*)&sQ[(r0 + 8) * 72 + k0 + l2];
        qf[ks][2] = *(const uint32_t*)&sQ[(r0) * 72 + k0 + l2 + 8];
        qf[ks][3] = *(const uint32_t*)&sQ[(r0 + 8) * 72 + k0 + l2 + 8];
    }

    float m0 = -1e30f, m1 = -1e30f;
    float o[9][4];                       // o[8] = l accumulator (ones-column)
#pragma unroll
    for (int n = 0; n < 9; n++)
#pragma unroll
        for (int c = 0; c < 4; c++) o[n][c] = 0.f;

    int st = 0;
    for (int kt = 0; kt <= qt; kt++) {
        CPA_WAIT1();
        __syncthreads();

        const __half* sKc = sh + 4608 + st * 4608;
        const __half* sVc = sh + 18432 + st * 4608;

        float s[4][4];
#pragma unroll
        for (int n = 0; n < 4; n++)
#pragma unroll
            for (int c = 0; c < 4; c++) s[n][c] = 0.f;

#pragma unroll
        for (int ks = 0; ks < 4; ks++) {
            int k0 = 16 * ks;
#pragma unroll
            for (int n = 0; n < 4; n++) {
                int kr = 32 * g + 8 * n + gid;
                uint32_t b0 = *(const uint32_t*)&sKc[kr * 72 + k0 + l2];
                uint32_t b1 = *(const uint32_t*)&sKc[kr * 72 + k0 + l2 + 8];
                mma_f16(s[n], qf[ks][0], qf[ks][1], qf[ks][2], qf[ks][3], b0, b1);
            }
        }

        // Causal mask only (Q carries scale)
        if (kt == qt) {
#pragma unroll
            for (int n = 0; n < 4; n++) {
                int c0 = 32 * g + 8 * n + l2;
                if (c0     > r0    ) s[n][0] = -1e30f;
                if (c0 + 1 > r0    ) s[n][1] = -1e30f;
                if (c0     > r0 + 8) s[n][2] = -1e30f;
                if (c0 + 1 > r0 + 8) s[n][3] = -1e30f;
            }
        }

        float mx0 = fmaxf(fmaxf(s[0][0], s[0][1]), fmaxf(s[1][0], s[1][1]));
        mx0 = fmaxf(mx0, fmaxf(fmaxf(s[2][0], s[2][1]), fmaxf(s[3][0], s[3][1])));
        float mx1 = fmaxf(fmaxf(s[0][2], s[0][3]), fmaxf(s[1][2], s[1][3]));
        mx1 = fmaxf(mx1, fmaxf(fmaxf(s[2][2], s[2][3]), fmaxf(s[3][2], s[3][3])));

        __half2 hmx = __floats2half2_rn(mx0, mx1);
        hmx = __hmax2(hmx, u32_to_h2(__shfl_xor_sync(0xffffffffu, h2_to_u32(hmx), 1)));
        hmx = __hmax2(hmx, u32_to_h2(__shfl_xor_sync(0xffffffffu, h2_to_u32(hmx), 2)));
        float2 fmx = __half22float2(hmx);

        float mn0 = fmaxf(m0, fmx.x);
        float mn1 = fmaxf(m1, fmx.y);
        float alpha0 = ex2(m0 - mn0);
        float alpha1 = ex2(m1 - mn1);
        m0 = mn0; m1 = mn1;

        // P = 2^(s - mn), packed fp16 pairs via ex2.approx.f16x2
        uint32_t p[8];
#pragma unroll
        for (int n = 0; n < 4; n++) {
            p[2 * n]     = ex2_h2(h2_to_u32(__floats2half2_rn(s[n][0] - mn0, s[n][1] - mn0)));
            p[2 * n + 1] = ex2_h2(h2_to_u32(__floats2half2_rn(s[n][2] - mn1, s[n][3] - mn1)));
        }

#pragma unroll
        for (int n = 0; n < 9; n++) {
            o[n][0] *= alpha0; o[n][1] *= alpha0;
            o[n][2] *= alpha1; o[n][3] *= alpha1;
        }

        // PV(kt): 8 real n-tiles + ones-column l tile
#pragma unroll
        for (int ks = 0; ks < 2; ks++) {
            uint32_t a0 = p[4 * ks + 0];
            uint32_t a1 = p[4 * ks + 1];
            uint32_t a2 = p[4 * ks + 2];
            uint32_t a3 = p[4 * ks + 3];
            int kb = 32 * g + 16 * ks + l2;
#pragma unroll
            for (int n = 0; n < 8; n++) {
                int vr = 8 * n + gid;
                uint32_t b0 = *(const uint32_t*)&sVc[vr * 72 + kb];
                uint32_t b1 = *(const uint32_t*)&sVc[vr * 72 + kb + 8];
                mma_f16(o[n], a0, a1, a2, a3, b0, b1);
            }
            mma_f16(o[8], a0, a1, a2, a3, ONES_H2, ONES_H2);   // l accumulator
        }

        // Prefetch tile kt+2 into slot (st+2)%3
        if (kt + 2 <= qt) {
            int ps = st + 2;
            if (ps >= 3) ps -= 3;
#pragma unroll
            for (int i = 0; i < 2; i++) {
                int id = t + i * 256;
                int r  = id >> 3;
                int ch = id & 7;
                CPA16(su + 9216 + ps * 9216 + r * 144 + 16 * ch,
                      Kg + (size_t)((kt + 2) * 64 + r) * HEAD + 8 * ch);
                CPA16(su + 36864 + ps * 9216 + r * 144 + 16 * ch,
                      Vg + (size_t)r * SEQ + (kt + 2) * 64 + 8 * ch);
            }
        }
        CPA_COMMIT();
        if (++st == 3) st = 0;
    }

    CPA_WAIT0();
    __syncthreads();

    const float l0 = o[8][0];            // row r0 sum (group-partial)
    const float l1 = o[8][2];            // row r0+8 sum

    // ---- Merge the two groups' partial (m, l, O) ----
    float* sML = (float*)smraw;
    if (l3 == 0) {
        sML[((g * 64 + r0)     << 1) + 0] = m0;
        sML[((g * 64 + r0)     << 1) + 1] = l0;
        sML[((g * 64 + r0 + 8) << 1) + 0] = m1;
        sML[((g * 64 + r0 + 8) << 1) + 1] = l1;
    }
    __syncthreads();
    const int og = 1 - g;
    float mo0 = sML[((og * 64 + r0)     << 1) + 0];
    float lo0 = sML[((og * 64 + r0)     << 1) + 1];
    float mo1 = sML[((og * 64 + r0 + 8) << 1) + 0];
    float lo1 = sML[((og * 64 + r0 + 8) << 1) + 1];

    float M0 = fmaxf(m0, mo0), M1 = fmaxf(m1, mo1);
    float sc0 = ex2(m0 - M0), sc1 = ex2(m1 - M1);
    float L0 = l0 * sc0 + lo0 * ex2(mo0 - M0);
    float L1 = l1 * sc1 + lo1 * ex2(mo1 - M1);

#pragma unroll
    for (int n = 0; n < 8; n++) {
        o[n][0] *= sc0; o[n][1] *= sc0;
        o[n][2] *= sc1; o[n][3] *= sc1;
    }

    float* sOB = (float*)(smraw + 9216);
    if (g == 1) {
#pragma unroll
        for (int n = 0; n < 8; n++) {
            int cb = 8 * n + l2;
            sOB[(r0) * 68 + cb + 0]     = o[n][0];
            sOB[(r0) * 68 + cb + 1]     = o[n][1];
            sOB[(r0 + 8) * 68 + cb + 0] = o[n][2];
            sOB[(r0 + 8) * 68 + cb + 1] = o[n][3];
        }
    }
    __syncthreads();
    if (g == 0) {
        float inv0 = 1.f / L0;
        float inv1 = 1.f / L1;
        size_t orow0 = (size_t)b * SEQ + qt * 64 + r0;
#pragma unroll
        for (int n = 0; n < 8; n++) {
            int cb = 8 * n + l2;
            float2 v0, v1;
            v0.x = (o[n][0] + sOB[(r0) * 68 + cb + 0])     * inv0;
            v0.y = (o[n][1] + sOB[(r0) * 68 + cb + 1])     * inv0;
            v1.x = (o[n][2] + sOB[(r0 + 8) * 68 + cb + 0]) * inv1;
            v1.y = (o[n][3] + sOB[(r0 + 8) * 68 + cb + 1]) * inv1;
            *(float2*)&out[orow0 * HEAD + cb]       = v0;
            *(float2*)&out[(orow0 + 8) * HEAD + cb] = v1;
        }
    }
}

extern "C" void kernel_launch(void* const* d_in, const int* in_sizes, int n_in,
                              void* d_out, int out_size)
{
    const float* x  = (const float*)d_in[0];
    const float* Wq = (const float*)d_in[1];
    const float* bq = (const float*)d_in[2];
    const float* Wk = (const float*)d_in[3];
    const float* bk = (const float*)d_in[4];
    const float* Wv = (const float*)d_in[5];
    const float* bv = (const float*)d_in[6];
    float* out = (float*)d_out;

    const size_t QKV_SMEM = (size_t)45056 * sizeof(float);   // 180224 B
    cudaFuncSetAttribute(qkv_fused_kernel, cudaFuncAttributeMaxDynamicSharedMemorySize,
                         (int)QKV_SMEM);
    qkv_fused_kernel<<<SEQ * BATCH / 128, 256, QKV_SMEM>>>(x, Wq, bq, Wk, bk, Wv, bv);

    const size_t FLASH_SMEM = 64512;     // bytes: Q 9216 + K 3x9216 + Vt 3x9216
    cudaFuncSetAttribute(flash_kernel, cudaFuncAttributeMaxDynamicSharedMemorySize,
                         (int)FLASH_SMEM);
    flash_kernel<<<SEQ / 64 * BATCH, 256, FLASH_SMEM>>>(out);
}

// round 16
// speedup vs baseline: 1.1564x; 1.1096x over previous
#include <cuda_runtime.h>
#include <cuda_fp16.h>
#include <cstdint>

#define EMBED 768
#define HEAD 64
#define SEQ 4096
#define BATCH 4

// Projections, fp16. g_Qh pre-scaled by 0.125*log2(e) (softmax in log2 domain).
// g_Qh/g_Kh: [B*T, 64] row-major. g_Vth: [B][64 head][4096 seq]
__device__ __half g_Qh[BATCH * SEQ * HEAD];
__device__ __half g_Kh[BATCH * SEQ * HEAD];
__device__ __half g_Vth[BATCH * HEAD * SEQ];
// fp16 transposed weights: g_WTh[m][n][e] = (half)W_m[e][n]
__device__ __half g_WTh[3 * HEAD * EMBED];

#define QSCALE 0.18033688f   // 0.125 * log2(e)
#define ONES_H2 0x3C003C00u  // half2(1.0, 1.0)

__device__ __forceinline__ uint32_t h2_to_u32(__half2 h) {
    union { __half2 h; uint32_t u; } cvt;
    cvt.h = h;
    return cvt.u;
}
__device__ __forceinline__ __half2 u32_to_h2(uint32_t u) {
    union { uint32_t u; __half2 h; } cvt;
    cvt.u = u;
    return cvt.h;
}
__device__ __forceinline__ float ex2(float x) {
    float r;
    asm("ex2.approx.ftz.f32 %0, %1;" : "=f"(r) : "f"(x));
    return r;
}
__device__ __forceinline__ uint32_t ex2_h2(uint32_t x) {
    uint32_t r;
    asm("ex2.approx.f16x2 %0, %1;" : "=r"(r) : "r"(x));
    return r;
}

// fp16: D(16x8,f32) += A(16x16,f16) * B(16x8,f16)
__device__ __forceinline__ void mma_f16(float c[4],
    uint32_t a0, uint32_t a1, uint32_t a2, uint32_t a3,
    uint32_t b0, uint32_t b1)
{
    asm volatile(
        "mma.sync.aligned.m16n8k16.row.col.f32.f16.f16.f32 "
        "{%0,%1,%2,%3}, {%4,%5,%6,%7}, {%8,%9}, {%0,%1,%2,%3};"
        : "+f"(c[0]), "+f"(c[1]), "+f"(c[2]), "+f"(c[3])
        : "r"(a0), "r"(a1), "r"(a2), "r"(a3), "r"(b0), "r"(b1));
}

__device__ __forceinline__ uint32_t s2u(const void* p) {
    uint32_t a;
    asm("{ .reg .u64 t; cvta.to.shared.u64 t, %1; cvt.u32.u64 %0, t; }"
        : "=r"(a) : "l"(p));
    return a;
}

#define CPA16(dst, src) \
    asm volatile("cp.async.cg.shared.global [%0], [%1], 16;" :: "r"(dst), "l"(src) : "memory")
#define CPA_COMMIT() asm volatile("cp.async.commit_group;" ::: "memory")
#define CPA_WAIT1()  asm volatile("cp.async.wait_group 1;" ::: "memory")
#define CPA_WAIT0()  asm volatile("cp.async.wait_group 0;" ::: "memory")

// ---------------------------------------------------------------------------
// Weight prep: g_WTh[m][n][e] = (half)W_m[e][n], via smem tile transpose.
// Coalesced loads (consecutive n) and stores (consecutive e). 36 blocks.
// ---------------------------------------------------------------------------
__global__ void wprep_kernel(const float* __restrict__ Wq,
                             const float* __restrict__ Wk,
                             const float* __restrict__ Wv)
{
    __shared__ float tile[64][65];
    const int m  = blockIdx.x / 12;
    const int e0 = (blockIdx.x % 12) * 64;
    const float* __restrict__ W = (m == 0) ? Wq : (m == 1) ? Wk : Wv;
    const int t = threadIdx.x;

#pragma unroll
    for (int i = 0; i < 16; i++) {
        int idx = t + i * 256;
        int r = idx >> 6;           // e within chunk
        int n = idx & 63;
        tile[r][n] = W[(size_t)(e0 + r) * HEAD + n];
    }
    __syncthreads();
#pragma unroll
    for (int i = 0; i < 16; i++) {
        int idx = t + i * 256;
        int n = idx >> 6;
        int c = idx & 63;           // e within chunk
        g_WTh[(size_t)m * HEAD * EMBED + (size_t)n * EMBED + e0 + c] =
            __float2half_rn(tile[c][n]);
    }
}

// ---------------------------------------------------------------------------
// Fused QKV projection, fp16 m16n8k16. 2(M) x 4(N) warp decomposition.
// W^T chunks cp.async double-buffered (fp16, [n][e]); x converted fp32->fp16
// with a software pipeline: STS(ch+1) after top barrier, LDG(ch+2) before
// compute (held in regs across the iteration).
// Grid = 128 blocks (single wave), 256 threads.
// smem (halves): X0[0,9216) X1[9216,18432)
//                W(stage s, matrix m) at 18432 + s*13824 + m*4608  (64x72)
// Total 46080 halves = 92160 B.
// ---------------------------------------------------------------------------
__global__ __launch_bounds__(256, 1) void qkv_fused_kernel(
    const float* __restrict__ x,
    const float* __restrict__ bq,
    const float* __restrict__ bk,
    const float* __restrict__ bv)
{
    extern __shared__ __align__(16) __half qsh[];
    const int XS = 9216, WBASE = 18432, WSTG = 13824, WMAT = 4608;
    const int NCH = EMBED / 64;          // 12 chunks

    const int t    = threadIdx.x;
    const int lane = t & 31;
    const int warp = t >> 5;
    const int mg   = warp >> 2;          // row-group 0/1 (64 rows)
    const int cg   = warp & 3;           // col-group 0..3
    const int gid  = lane >> 2;
    const int l3   = lane & 3;
    const int l2   = 2 * l3;
    const int row0 = blockIdx.x * 128;

    const uint32_t su = s2u(qsh);

    // thread's x-slice coordinates (8 float4 per chunk)
    int xr[8], xc[8];
#pragma unroll
    for (int i = 0; i < 8; i++) {
        int id = t + i * 256;
        xr[i] = id >> 4;
        xc[i] = (id & 15) << 2;
    }

    // ---- prologue ----
    // cp.async W chunks 0 and 1
#pragma unroll
    for (int st = 0; st < 2; st++) {
        uint32_t wbase = su + (WBASE + st * WSTG) * 2;
#pragma unroll
        for (int i = 0; i < 6; i++) {        // 3 mats x 64 rows x 128B = 1536 chunks16
            int id = t + i * 256;
            int m  = id / 512;
            int rm = id - m * 512;
            int r  = rm >> 3;
            int ch = rm & 7;
            CPA16(wbase + (m * WMAT + r * 72) * 2 + 16 * ch,
                  g_WTh + (size_t)m * HEAD * EMBED + (size_t)r * EMBED + st * 64 + 8 * ch);
        }
        CPA_COMMIT();
    }
    // x chunk 0: LDG + cvt + STS into X0
    {
        float4 h[8];
#pragma unroll
        for (int i = 0; i < 8; i++)
            h[i] = *(const float4*)&x[(size_t)(row0 + xr[i]) * EMBED + 0 + xc[i]];
#pragma unroll
        for (int i = 0; i < 8; i++) {
            uint2 v;
            v.x = h2_to_u32(__floats2half2_rn(h[i].x, h[i].y));
            v.y = h2_to_u32(__floats2half2_rn(h[i].z, h[i].w));
            *(uint2*)&qsh[xr[i] * 72 + xc[i]] = v;
        }
    }
    // x chunk 1: LDG into held regs
    float4 hx[8];
#pragma unroll
    for (int i = 0; i < 8; i++)
        hx[i] = *(const float4*)&x[(size_t)(row0 + xr[i]) * EMBED + 64 + xc[i]];

    float o[4][3][2][4];
#pragma unroll
    for (int mt = 0; mt < 4; mt++)
#pragma unroll
        for (int m = 0; m < 3; m++)
#pragma unroll
            for (int j = 0; j < 2; j++)
#pragma unroll
                for (int c = 0; c < 4; c++) o[mt][m][j][c] = 0.f;

    for (int chk = 0; chk < NCH; chk++) {
        CPA_WAIT1();                     // W(chk) landed
        __syncthreads();                 // X(chk) STS visible; buffers sealed

        // STS x(chk+1) from held regs into the other x buffer
        if (chk + 1 < NCH) {
            __half* xd = qsh + ((chk + 1) & 1) * XS;
#pragma unroll
            for (int i = 0; i < 8; i++) {
                uint2 v;
                v.x = h2_to_u32(__floats2half2_rn(hx[i].x, hx[i].y));
                v.y = h2_to_u32(__floats2half2_rn(hx[i].z, hx[i].w));
                *(uint2*)&xd[xr[i] * 72 + xc[i]] = v;
            }
        }
        // LDG x(chk+2) into held regs (latency hidden under compute)
        if (chk + 2 < NCH) {
            int e0 = (chk + 2) * 64;
#pragma unroll
            for (int i = 0; i < 8; i++)
                hx[i] = *(const float4*)&x[(size_t)(row0 + xr[i]) * EMBED + e0 + xc[i]];
        }

        const __half* sx = qsh + (chk & 1) * XS;
        const __half* sw = qsh + WBASE + (chk & 1) * WSTG;

#pragma unroll
        for (int ks = 0; ks < 4; ks++) {
            int k0 = 16 * ks;
            uint32_t af[4][4];
#pragma unroll
            for (int mt = 0; mt < 4; mt++) {
                int row = 64 * mg + 16 * mt + gid;
                af[mt][0] = *(const uint32_t*)&sx[(row) * 72 + k0 + l2];
                af[mt][1] = *(const uint32_t*)&sx[(row + 8) * 72 + k0 + l2];
                af[mt][2] = *(const uint32_t*)&sx[(row) * 72 + k0 + l2 + 8];
                af[mt][3] = *(const uint32_t*)&sx[(row + 8) * 72 + k0 + l2 + 8];
            }
#pragma unroll
            for (int m = 0; m < 3; m++) {
                const __half* swm = sw + m * WMAT;
#pragma unroll
                for (int j = 0; j < 2; j++) {
                    int n = 2 * cg + j;
                    uint32_t b0 = *(const uint32_t*)&swm[(8 * n + gid) * 72 + k0 + l2];
                    uint32_t b1 = *(const uint32_t*)&swm[(8 * n + gid) * 72 + k0 + l2 + 8];
#pragma unroll
                    for (int mt = 0; mt < 4; mt++)
                        mma_f16(o[mt][m][j], af[mt][0], af[mt][1], af[mt][2], af[mt][3], b0, b1);
                }
            }
        }

        __syncthreads();                 // everyone done reading W(chk) buffer

        // cp.async W(chk+2) into the buffer just freed
        if (chk + 2 < NCH) {
            int e0 = (chk + 2) * 64;
            uint32_t wbase = su + (WBASE + (chk & 1) * WSTG) * 2;
#pragma unroll
            for (int i = 0; i < 6; i++) {
                int id = t + i * 256;
                int m  = id / 512;
                int rm = id - m * 512;
                int r  = rm >> 3;
                int ch = rm & 7;
                CPA16(wbase + (m * WMAT + r * 72) * 2 + 16 * ch,
                      g_WTh + (size_t)m * HEAD * EMBED + (size_t)r * EMBED + e0 + 8 * ch);
            }
        }
        CPA_COMMIT();
    }
    CPA_WAIT0();

    const int bb = row0 / SEQ;
    __half* vt = g_Vth + (size_t)bb * HEAD * SEQ;

#pragma unroll
    for (int mt = 0; mt < 4; mt++) {
        const int rowA = row0 + 64 * mg + 16 * mt + gid;
        const int rowB = rowA + 8;
        const int seqA = rowA - bb * SEQ;
#pragma unroll
        for (int j = 0; j < 2; j++) {
            int n  = 2 * cg + j;
            int cb = 8 * n + l2;
            {
                float b0 = bq[cb], b1 = bq[cb + 1];
                *(__half2*)&g_Qh[(size_t)rowA * HEAD + cb] =
                    __floats2half2_rn((o[mt][0][j][0] + b0) * QSCALE,
                                      (o[mt][0][j][1] + b1) * QSCALE);
                *(__half2*)&g_Qh[(size_t)rowB * HEAD + cb] =
                    __floats2half2_rn((o[mt][0][j][2] + b0) * QSCALE,
                                      (o[mt][0][j][3] + b1) * QSCALE);
            }
            {
                float b0 = bk[cb], b1 = bk[cb + 1];
                *(__half2*)&g_Kh[(size_t)rowA * HEAD + cb] =
                    __floats2half2_rn(o[mt][1][j][0] + b0, o[mt][1][j][1] + b1);
                *(__half2*)&g_Kh[(size_t)rowB * HEAD + cb] =
                    __floats2half2_rn(o[mt][1][j][2] + b0, o[mt][1][j][3] + b1);
            }
            {
                float b0 = bv[cb], b1 = bv[cb + 1];
                vt[(size_t)(cb)     * SEQ + seqA]     = __float2half_rn(o[mt][2][j][0] + b0);
                vt[(size_t)(cb + 1) * SEQ + seqA]     = __float2half_rn(o[mt][2][j][1] + b1);
                vt[(size_t)(cb)     * SEQ + seqA + 8] = __float2half_rn(o[mt][2][j][2] + b0);
                vt[(size_t)(cb + 1) * SEQ + seqA + 8] = __float2half_rn(o[mt][2][j][3] + b1);
            }
        }
    }
}

// ---------------------------------------------------------------------------
// Flash attention (unchanged from Round 15): causal, fp16 m16n8k16, split-kn,
// ones-column l accumulator, ex2.approx.f16x2 softmax, 3-stage cp.async ring,
// one __syncthreads per iter, LPT-balanced tiles.
// smem bytes: Q[0,9216) K stage s at 9216+9216s (s<3), V at 36864+9216s.
// ---------------------------------------------------------------------------
__global__ __launch_bounds__(256, 2) void flash_kernel(float* __restrict__ out)
{
    extern __shared__ __align__(16) unsigned char smraw[];
    __half* sh = (__half*)smraw;
    __half* sQ = sh;                     // 64 x 72 halves

    const int bid = blockIdx.x;
    const int rr  = (bid < 148) ? bid : 403 - bid;
    const int qt  = 63 - (rr >> 2);
    const int b   = rr & 3;

    const int t    = threadIdx.x;
    const int lane = t & 31;
    const int warp = t >> 5;
    const int g    = warp >> 2;          // column-group 0/1
    const int w16  = (warp & 3) << 4;
    const int gid  = lane >> 2;
    const int l3   = lane & 3;
    const int r0   = w16 + gid;
    const int l2   = 2 * l3;

    const __half* __restrict__ Qg = g_Qh + (size_t)b * SEQ * HEAD;
    const __half* __restrict__ Kg = g_Kh + (size_t)b * SEQ * HEAD;
    const __half* __restrict__ Vg = g_Vth + (size_t)b * HEAD * SEQ;

    const uint32_t su = s2u(sh);

    // g0: Q + K0 + V0
#pragma unroll
    for (int i = 0; i < 2; i++) {
        int id = t + i * 256;
        int r  = id >> 3;
        int ch = id & 7;
        CPA16(su + r * 144 + 16 * ch, Qg + (size_t)(qt * 64 + r) * HEAD + 8 * ch);
        CPA16(su + 9216 + r * 144 + 16 * ch, Kg + (size_t)r * HEAD + 8 * ch);
        CPA16(su + 36864 + r * 144 + 16 * ch, Vg + (size_t)r * SEQ + 8 * ch);
    }
    CPA_COMMIT();
    // g1: K1 + V1
#pragma unroll
    for (int i = 0; i < 2; i++) {
        int id = t + i * 256;
        int r  = id >> 3;
        int ch = id & 7;
        CPA16(su + 9216 + 9216 + r * 144 + 16 * ch,
              Kg + (size_t)(64 + r) * HEAD + 8 * ch);
        CPA16(su + 36864 + 9216 + r * 144 + 16 * ch,
              Vg + (size_t)r * SEQ + 64 + 8 * ch);
    }
    CPA_COMMIT();

    CPA_WAIT1();
    __syncthreads();
    uint32_t qf[4][4];
#pragma unroll
    for (int ks = 0; ks < 4; ks++) {
        int k0 = 16 * ks;
        qf[ks][0] = *(const uint32_t*)&sQ[(r0) * 72 + k0 + l2];
        qf[ks][1] = *(const uint32_t*)&sQ[(r0 + 8) * 72 + k0 + l2];
        qf[ks][2] = *(const uint32_t*)&sQ[(r0) * 72 + k0 + l2 + 8];
        qf[ks][3] = *(const uint32_t*)&sQ[(r0 + 8) * 72 + k0 + l2 + 8];
    }

    float m0 = -1e30f, m1 = -1e30f;
    float o[9][4];                       // o[8] = l accumulator (ones-column)
#pragma unroll
    for (int n = 0; n < 9; n++)
#pragma unroll
        for (int c = 0; c < 4; c++) o[n][c] = 0.f;

    int st = 0;
    for (int kt = 0; kt <= qt; kt++) {
        CPA_WAIT1();
        __syncthreads();

        const __half* sKc = sh + 4608 + st * 4608;
        const __half* sVc = sh + 18432 + st * 4608;

        float s[4][4];
#pragma unroll
        for (int n = 0; n < 4; n++)
#pragma unroll
            for (int c = 0; c < 4; c++) s[n][c] = 0.f;

#pragma unroll
        for (int ks = 0; ks < 4; ks++) {
            int k0 = 16 * ks;
#pragma unroll
            for (int n = 0; n < 4; n++) {
                int kr = 32 * g + 8 * n + gid;
                uint32_t b0 = *(const uint32_t*)&sKc[kr * 72 + k0 + l2];
                uint32_t b1 = *(const uint32_t*)&sKc[kr * 72 + k0 + l2 + 8];
                mma_f16(s[n], qf[ks][0], qf[ks][1], qf[ks][2], qf[ks][3], b0, b1);
            }
        }

        if (kt == qt) {
#pragma unroll
            for (int n = 0; n < 4; n++) {
                int c0 = 32 * g + 8 * n + l2;
                if (c0     > r0    ) s[n][0] = -1e30f;
                if (c0 + 1 > r0    ) s[n][1] = -1e30f;
                if (c0     > r0 + 8) s[n][2] = -1e30f;
                if (c0 + 1 > r0 + 8) s[n][3] = -1e30f;
            }
        }

        float mx0 = fmaxf(fmaxf(s[0][0], s[0][1]), fmaxf(s[1][0], s[1][1]));
        mx0 = fmaxf(mx0, fmaxf(fmaxf(s[2][0], s[2][1]), fmaxf(s[3][0], s[3][1])));
        float mx1 = fmaxf(fmaxf(s[0][2], s[0][3]), fmaxf(s[1][2], s[1][3]));
        mx1 = fmaxf(mx1, fmaxf(fmaxf(s[2][2], s[2][3]), fmaxf(s[3][2], s[3][3])));

        __half2 hmx = __floats2half2_rn(mx0, mx1);
        hmx = __hmax2(hmx, u32_to_h2(__shfl_xor_sync(0xffffffffu, h2_to_u32(hmx), 1)));
        hmx = __hmax2(hmx, u32_to_h2(__shfl_xor_sync(0xffffffffu, h2_to_u32(hmx), 2)));
        float2 fmx = __half22float2(hmx);

        float mn0 = fmaxf(m0, fmx.x);
        float mn1 = fmaxf(m1, fmx.y);
        float alpha0 = ex2(m0 - mn0);
        float alpha1 = ex2(m1 - mn1);
        m0 = mn0; m1 = mn1;

        uint32_t p[8];
#pragma unroll
        for (int n = 0; n < 4; n++) {
            p[2 * n]     = ex2_h2(h2_to_u32(__floats2half2_rn(s[n][0] - mn0, s[n][1] - mn0)));
            p[2 * n + 1] = ex2_h2(h2_to_u32(__floats2half2_rn(s[n][2] - mn1, s[n][3] - mn1)));
        }

#pragma unroll
        for (int n = 0; n < 9; n++) {
            o[n][0] *= alpha0; o[n][1] *= alpha0;
            o[n][2] *= alpha1; o[n][3] *= alpha1;
        }

#pragma unroll
        for (int ks = 0; ks < 2; ks++) {
            uint32_t a0 = p[4 * ks + 0];
            uint32_t a1 = p[4 * ks + 1];
            uint32_t a2 = p[4 * ks + 2];
            uint32_t a3 = p[4 * ks + 3];
            int kb = 32 * g + 16 * ks + l2;
#pragma unroll
            for (int n = 0; n < 8; n++) {
                int vr = 8 * n + gid;
                uint32_t b0 = *(const uint32_t*)&sVc[vr * 72 + kb];
                uint32_t b1 = *(const uint32_t*)&sVc[vr * 72 + kb + 8];
                mma_f16(o[n], a0, a1, a2, a3, b0, b1);
            }
            mma_f16(o[8], a0, a1, a2, a3, ONES_H2, ONES_H2);
        }

        if (kt + 2 <= qt) {
            int ps = st + 2;
            if (ps >= 3) ps -= 3;
#pragma unroll
            for (int i = 0; i < 2; i++) {
                int id = t + i * 256;
                int r  = id >> 3;
                int ch = id & 7;
                CPA16(su + 9216 + ps * 9216 + r * 144 + 16 * ch,
                      Kg + (size_t)((kt + 2) * 64 + r) * HEAD + 8 * ch);
                CPA16(su + 36864 + ps * 9216 + r * 144 + 16 * ch,
                      Vg + (size_t)r * SEQ + (kt + 2) * 64 + 8 * ch);
            }
        }
        CPA_COMMIT();
        if (++st == 3) st = 0;
    }

    CPA_WAIT0();
    __syncthreads();

    const float l0 = o[8][0];
    const float l1 = o[8][2];

    float* sML = (float*)smraw;
    if (l3 == 0) {
        sML[((g * 64 + r0)     << 1) + 0] = m0;
        sML[((g * 64 + r0)     << 1) + 1] = l0;
        sML[((g * 64 + r0 + 8) << 1) + 0] = m1;
        sML[((g * 64 + r0 + 8) << 1) + 1] = l1;
    }
    __syncthreads();
    const int og = 1 - g;
    float mo0 = sML[((og * 64 + r0)     << 1) + 0];
    float lo0 = sML[((og * 64 + r0)     << 1) + 1];
    float mo1 = sML[((og * 64 + r0 + 8) << 1) + 0];
    float lo1 = sML[((og * 64 + r0 + 8) << 1) + 1];

    float M0 = fmaxf(m0, mo0), M1 = fmaxf(m1, mo1);
    float sc0 = ex2(m0 - M0), sc1 = ex2(m1 - M1);
    float L0 = l0 * sc0 + lo0 * ex2(mo0 - M0);
    float L1 = l1 * sc1 + lo1 * ex2(mo1 - M1);

#pragma unroll
    for (int n = 0; n < 8; n++) {
        o[n][0] *= sc0; o[n][1] *= sc0;
        o[n][2] *= sc1; o[n][3] *= sc1;
    }

    float* sOB = (float*)(smraw + 9216);
    if (g == 1) {
#pragma unroll
        for (int n = 0; n < 8; n++) {
            int cb = 8 * n + l2;
            sOB[(r0) * 68 + cb + 0]     = o[n][0];
            sOB[(r0) * 68 + cb + 1]     = o[n][1];
            sOB[(r0 + 8) * 68 + cb + 0] = o[n][2];
            sOB[(r0 + 8) * 68 + cb + 1] = o[n][3];
        }
    }
    __syncthreads();
    if (g == 0) {
        float inv0 = 1.f / L0;
        float inv1 = 1.f / L1;
        size_t orow0 = (size_t)b * SEQ + qt * 64 + r0;
#pragma unroll
        for (int n = 0; n < 8; n++) {
            int cb = 8 * n + l2;
            float2 v0, v1;
            v0.x = (o[n][0] + sOB[(r0) * 68 + cb + 0])     * inv0;
            v0.y = (o[n][1] + sOB[(r0) * 68 + cb + 1])     * inv0;
            v1.x = (o[n][2] + sOB[(r0 + 8) * 68 + cb + 0]) * inv1;
            v1.y = (o[n][3] + sOB[(r0 + 8) * 68 + cb + 1]) * inv1;
            *(float2*)&out[orow0 * HEAD + cb]       = v0;
            *(float2*)&out[(orow0 + 8) * HEAD + cb] = v1;
        }
    }
}

extern "C" void kernel_launch(void* const* d_in, const int* in_sizes, int n_in,
                              void* d_out, int out_size)
{
    const float* x  = (const float*)d_in[0];
    const float* Wq = (const float*)d_in[1];
    const float* bq = (const float*)d_in[2];
    const float* Wk = (const float*)d_in[3];
    const float* bk = (const float*)d_in[4];
    const float* Wv = (const float*)d_in[5];
    const float* bv = (const float*)d_in[6];
    float* out = (float*)d_out;

    wprep_kernel<<<36, 256>>>(Wq, Wk, Wv);

    const size_t QKV_SMEM = 92160;       // bytes: x 2x18432 + W 2x27648
    cudaFuncSetAttribute(qkv_fused_kernel, cudaFuncAttributeMaxDynamicSharedMemorySize,
                         (int)QKV_SMEM);
    qkv_fused_kernel<<<SEQ * BATCH / 128, 256, QKV_SMEM>>>(x, bq, bk, bv);

    const size_t FLASH_SMEM = 64512;     // bytes: Q 9216 + K 3x9216 + Vt 3x9216
    cudaFuncSetAttribute(flash_kernel, cudaFuncAttributeMaxDynamicSharedMemorySize,
                         (int)FLASH_SMEM);
    flash_kernel<<<SEQ / 64 * BATCH, 256, FLASH_SMEM>>>(out);
}

// round 17
// speedup vs baseline: 1.1944x; 1.0329x over previous
#include <cuda_runtime.h>
#include <cuda_fp16.h>
#include <cstdint>

#define EMBED 768
#define HEAD 64
#define SEQ 4096
#define BATCH 4

// Projections, fp16. g_Qh pre-scaled by 0.125*log2(e) (softmax in log2 domain).
// g_Qh/g_Kh: [B*T, 64] row-major. g_Vth: [B][64 head][4096 seq]
__device__ __half g_Qh[BATCH * SEQ * HEAD];
__device__ __half g_Kh[BATCH * SEQ * HEAD];
__device__ __half g_Vth[BATCH * HEAD * SEQ];
// fp16 transposed weights: g_WTh[m][n][e] = (half)W_m[e][n]
__device__ __half g_WTh[3 * HEAD * EMBED];

#define QSCALE 0.18033688f   // 0.125 * log2(e)
#define ONES_H2 0x3C003C00u  // half2(1.0, 1.0)

__device__ __forceinline__ uint32_t h2_to_u32(__half2 h) {
    union { __half2 h; uint32_t u; } cvt;
    cvt.h = h;
    return cvt.u;
}
__device__ __forceinline__ __half2 u32_to_h2(uint32_t u) {
    union { uint32_t u; __half2 h; } cvt;
    cvt.u = u;
    return cvt.h;
}
__device__ __forceinline__ float ex2(float x) {
    float r;
    asm("ex2.approx.ftz.f32 %0, %1;" : "=f"(r) : "f"(x));
    return r;
}
__device__ __forceinline__ uint32_t ex2_h2(uint32_t x) {
    uint32_t r;
    asm("ex2.approx.f16x2 %0, %1;" : "=r"(r) : "r"(x));
    return r;
}

// fp16: D(16x8,f32) += A(16x16,f16) * B(16x8,f16)
__device__ __forceinline__ void mma_f16(float c[4],
    uint32_t a0, uint32_t a1, uint32_t a2, uint32_t a3,
    uint32_t b0, uint32_t b1)
{
    asm volatile(
        "mma.sync.aligned.m16n8k16.row.col.f32.f16.f16.f32 "
        "{%0,%1,%2,%3}, {%4,%5,%6,%7}, {%8,%9}, {%0,%1,%2,%3};"
        : "+f"(c[0]), "+f"(c[1]), "+f"(c[2]), "+f"(c[3])
        : "r"(a0), "r"(a1), "r"(a2), "r"(a3), "r"(b0), "r"(b1));
}

// 4x (8x8 b16) matrices; per-lane row address in shared space
__device__ __forceinline__ void ldsm_x4(uint32_t& r0, uint32_t& r1,
                                        uint32_t& r2, uint32_t& r3, uint32_t addr)
{
    asm volatile("ldmatrix.sync.aligned.m8n8.x4.shared.b16 {%0,%1,%2,%3}, [%4];"
        : "=r"(r0), "=r"(r1), "=r"(r2), "=r"(r3) : "r"(addr));
}

__device__ __forceinline__ uint32_t s2u(const void* p) {
    uint32_t a;
    asm("{ .reg .u64 t; cvta.to.shared.u64 t, %1; cvt.u32.u64 %0, t; }"
        : "=r"(a) : "l"(p));
    return a;
}

#define CPA16(dst, src) \
    asm volatile("cp.async.cg.shared.global [%0], [%1], 16;" :: "r"(dst), "l"(src) : "memory")
#define CPA_COMMIT() asm volatile("cp.async.commit_group;" ::: "memory")
#define CPA_WAIT1()  asm volatile("cp.async.wait_group 1;" ::: "memory")
#define CPA_WAIT0()  asm volatile("cp.async.wait_group 0;" ::: "memory")

// ---------------------------------------------------------------------------
// Weight prep: g_WTh[m][n][e] = (half)W_m[e][n]. 144 blocks (3 x 12e x 4n),
// tile 64e x 16n; coalesced loads and stores.
// ---------------------------------------------------------------------------
__global__ void wprep_kernel(const float* __restrict__ Wq,
                             const float* __restrict__ Wk,
                             const float* __restrict__ Wv)
{
    __shared__ float tile[64][17];
    const int blk = blockIdx.x;
    const int m   = blk / 48;
    const int e0  = ((blk / 4) % 12) * 64;
    const int n0  = (blk & 3) * 16;
    const float* __restrict__ W = (m == 0) ? Wq : (m == 1) ? Wk : Wv;
    const int t = threadIdx.x;

#pragma unroll
    for (int i = 0; i < 4; i++) {
        int idx = t + i * 256;
        int r = idx >> 4;           // e within chunk
        int n = idx & 15;
        tile[r][n] = W[(size_t)(e0 + r) * HEAD + n0 + n];
    }
    __syncthreads();
#pragma unroll
    for (int i = 0; i < 4; i++) {
        int idx = t + i * 256;
        int n = idx >> 6;
        int c = idx & 63;           // e within chunk
        g_WTh[(size_t)m * HEAD * EMBED + (size_t)(n0 + n) * EMBED + e0 + c] =
            __float2half_rn(tile[c][n]);
    }
}

// ---------------------------------------------------------------------------
// Fused QKV projection (unchanged from Round 16): fp16 m16n8k16,
// 2(M) x 4(N) warp decomposition, double-buffered W cp.async + pipelined
// x conversion. Grid = 128 blocks, 256 threads.
// smem (halves): X0[0,9216) X1[9216,18432)
//                W(stage s, matrix m) at 18432 + s*13824 + m*4608  (64x72)
// ---------------------------------------------------------------------------
__global__ __launch_bounds__(256, 1) void qkv_fused_kernel(
    const float* __restrict__ x,
    const float* __restrict__ bq,
    const float* __restrict__ bk,
    const float* __restrict__ bv)
{
    extern __shared__ __align__(16) __half qsh[];
    const int XS = 9216, WBASE = 18432, WSTG = 13824, WMAT = 4608;
    const int NCH = EMBED / 64;

    const int t    = threadIdx.x;
    const int lane = t & 31;
    const int warp = t >> 5;
    const int mg   = warp >> 2;
    const int cg   = warp & 3;
    const int gid  = lane >> 2;
    const int l3   = lane & 3;
    const int l2   = 2 * l3;
    const int row0 = blockIdx.x * 128;

    const uint32_t su = s2u(qsh);

    int xr[8], xc[8];
#pragma unroll
    for (int i = 0; i < 8; i++) {
        int id = t + i * 256;
        xr[i] = id >> 4;
        xc[i] = (id & 15) << 2;
    }

#pragma unroll
    for (int st = 0; st < 2; st++) {
        uint32_t wbase = su + (WBASE + st * WSTG) * 2;
#pragma unroll
        for (int i = 0; i < 6; i++) {
            int id = t + i * 256;
            int m  = id / 512;
            int rm = id - m * 512;
            int r  = rm >> 3;
            int ch = rm & 7;
            CPA16(wbase + (m * WMAT + r * 72) * 2 + 16 * ch,
                  g_WTh + (size_t)m * HEAD * EMBED + (size_t)r * EMBED + st * 64 + 8 * ch);
        }
        CPA_COMMIT();
    }
    {
        float4 h[8];
#pragma unroll
        for (int i = 0; i < 8; i++)
            h[i] = *(const float4*)&x[(size_t)(row0 + xr[i]) * EMBED + 0 + xc[i]];
#pragma unroll
        for (int i = 0; i < 8; i++) {
            uint2 v;
            v.x = h2_to_u32(__floats2half2_rn(h[i].x, h[i].y));
            v.y = h2_to_u32(__floats2half2_rn(h[i].z, h[i].w));
            *(uint2*)&qsh[xr[i] * 72 + xc[i]] = v;
        }
    }
    float4 hx[8];
#pragma unroll
    for (int i = 0; i < 8; i++)
        hx[i] = *(const float4*)&x[(size_t)(row0 + xr[i]) * EMBED + 64 + xc[i]];

    float o[4][3][2][4];
#pragma unroll
    for (int mt = 0; mt < 4; mt++)
#pragma unroll
        for (int m = 0; m < 3; m++)
#pragma unroll
            for (int j = 0; j < 2; j++)
#pragma unroll
                for (int c = 0; c < 4; c++) o[mt][m][j][c] = 0.f;

    for (int chk = 0; chk < NCH; chk++) {
        CPA_WAIT1();
        __syncthreads();

        if (chk + 1 < NCH) {
            __half* xd = qsh + ((chk + 1) & 1) * XS;
#pragma unroll
            for (int i = 0; i < 8; i++) {
                uint2 v;
                v.x = h2_to_u32(__floats2half2_rn(hx[i].x, hx[i].y));
                v.y = h2_to_u32(__floats2half2_rn(hx[i].z, hx[i].w));
                *(uint2*)&xd[xr[i] * 72 + xc[i]] = v;
            }
        }
        if (chk + 2 < NCH) {
            int e0 = (chk + 2) * 64;
#pragma unroll
            for (int i = 0; i < 8; i++)
                hx[i] = *(const float4*)&x[(size_t)(row0 + xr[i]) * EMBED + e0 + xc[i]];
        }

        const __half* sx = qsh + (chk & 1) * XS;
        const __half* sw = qsh + WBASE + (chk & 1) * WSTG;

#pragma unroll
        for (int ks = 0; ks < 4; ks++) {
            int k0 = 16 * ks;
            uint32_t af[4][4];
#pragma unroll
            for (int mt = 0; mt < 4; mt++) {
                int row = 64 * mg + 16 * mt + gid;
                af[mt][0] = *(const uint32_t*)&sx[(row) * 72 + k0 + l2];
                af[mt][1] = *(const uint32_t*)&sx[(row + 8) * 72 + k0 + l2];
                af[mt][2] = *(const uint32_t*)&sx[(row) * 72 + k0 + l2 + 8];
                af[mt][3] = *(const uint32_t*)&sx[(row + 8) * 72 + k0 + l2 + 8];
            }
#pragma unroll
            for (int m = 0; m < 3; m++) {
                const __half* swm = sw + m * WMAT;
#pragma unroll
                for (int j = 0; j < 2; j++) {
                    int n = 2 * cg + j;
                    uint32_t b0 = *(const uint32_t*)&swm[(8 * n + gid) * 72 + k0 + l2];
                    uint32_t b1 = *(const uint32_t*)&swm[(8 * n + gid) * 72 + k0 + l2 + 8];
#pragma unroll
                    for (int mt = 0; mt < 4; mt++)
                        mma_f16(o[mt][m][j], af[mt][0], af[mt][1], af[mt][2], af[mt][3], b0, b1);
                }
            }
        }

        __syncthreads();

        if (chk + 2 < NCH) {
            int e0 = (chk + 2) * 64;
            uint32_t wbase = su + (WBASE + (chk & 1) * WSTG) * 2;
#pragma unroll
            for (int i = 0; i < 6; i++) {
                int id = t + i * 256;
                int m  = id / 512;
                int rm = id - m * 512;
                int r  = rm >> 3;
                int ch = rm & 7;
                CPA16(wbase + (m * WMAT + r * 72) * 2 + 16 * ch,
                      g_WTh + (size_t)m * HEAD * EMBED + (size_t)r * EMBED + e0 + 8 * ch);
            }
        }
        CPA_COMMIT();
    }
    CPA_WAIT0();

    const int bb = row0 / SEQ;
    __half* vt = g_Vth + (size_t)bb * HEAD * SEQ;

#pragma unroll
    for (int mt = 0; mt < 4; mt++) {
        const int rowA = row0 + 64 * mg + 16 * mt + gid;
        const int rowB = rowA + 8;
        const int seqA = rowA - bb * SEQ;
#pragma unroll
        for (int j = 0; j < 2; j++) {
            int n  = 2 * cg + j;
            int cb = 8 * n + l2;
            {
                float b0 = bq[cb], b1 = bq[cb + 1];
                *(__half2*)&g_Qh[(size_t)rowA * HEAD + cb] =
                    __floats2half2_rn((o[mt][0][j][0] + b0) * QSCALE,
                                      (o[mt][0][j][1] + b1) * QSCALE);
                *(__half2*)&g_Qh[(size_t)rowB * HEAD + cb] =
                    __floats2half2_rn((o[mt][0][j][2] + b0) * QSCALE,
                                      (o[mt][0][j][3] + b1) * QSCALE);
            }
            {
                float b0 = bk[cb], b1 = bk[cb + 1];
                *(__half2*)&g_Kh[(size_t)rowA * HEAD + cb] =
                    __floats2half2_rn(o[mt][1][j][0] + b0, o[mt][1][j][1] + b1);
                *(__half2*)&g_Kh[(size_t)rowB * HEAD + cb] =
                    __floats2half2_rn(o[mt][1][j][2] + b0, o[mt][1][j][3] + b1);
            }
            {
                float b0 = bv[cb], b1 = bv[cb + 1];
                vt[(size_t)(cb)     * SEQ + seqA]     = __float2half_rn(o[mt][2][j][0] + b0);
                vt[(size_t)(cb + 1) * SEQ + seqA]     = __float2half_rn(o[mt][2][j][1] + b1);
                vt[(size_t)(cb)     * SEQ + seqA + 8] = __float2half_rn(o[mt][2][j][2] + b0);
                vt[(size_t)(cb + 1) * SEQ + seqA + 8] = __float2half_rn(o[mt][2][j][3] + b1);
            }
        }
    }
}

// ---------------------------------------------------------------------------
// Flash attention: Round-15 structure with K/V fragments via ldmatrix.x4
// (8 LDSM for K + 8 LDSM for V per warp-iter, replacing 64 LDS.32).
// Lane-address pattern: tile = lane>>3, tr = lane&7; row stride 144B ->
// conflict-free (16r mod 128 all distinct).
// smem bytes: Q[0,9216) K stage s at 9216+9216s (s<3), V at 36864+9216s.
// ---------------------------------------------------------------------------
__global__ __launch_bounds__(256, 2) void flash_kernel(float* __restrict__ out)
{
    extern __shared__ __align__(16) unsigned char smraw[];
    __half* sh = (__half*)smraw;
    __half* sQ = sh;                     // 64 x 72 halves

    const int bid = blockIdx.x;
    const int rr  = (bid < 148) ? bid : 403 - bid;
    const int qt  = 63 - (rr >> 2);
    const int b   = rr & 3;

    const int t    = threadIdx.x;
    const int lane = t & 31;
    const int warp = t >> 5;
    const int g    = warp >> 2;          // column-group 0/1
    const int w16  = (warp & 3) << 4;
    const int gid  = lane >> 2;
    const int l3   = lane & 3;
    const int r0   = w16 + gid;
    const int l2   = 2 * l3;

    const __half* __restrict__ Qg = g_Qh + (size_t)b * SEQ * HEAD;
    const __half* __restrict__ Kg = g_Kh + (size_t)b * SEQ * HEAD;
    const __half* __restrict__ Vg = g_Vth + (size_t)b * HEAD * SEQ;

    const uint32_t su = s2u(sh);

    // ldmatrix lane offsets (bytes within a stage tile)
    const int tile = lane >> 3;          // 0..3
    const int tr   = lane & 7;
    const uint32_t koff = (uint32_t)((32 * g + 8 * (tile >> 1) + tr) * 144 + 16 * (tile & 1));
    const uint32_t voff = (uint32_t)((8 * (tile >> 1) + tr) * 144 + 16 * (tile & 1));

    // g0: Q + K0 + V0
#pragma unroll
    for (int i = 0; i < 2; i++) {
        int id = t + i * 256;
        int r  = id >> 3;
        int ch = id & 7;
        CPA16(su + r * 144 + 16 * ch, Qg + (size_t)(qt * 64 + r) * HEAD + 8 * ch);
        CPA16(su + 9216 + r * 144 + 16 * ch, Kg + (size_t)r * HEAD + 8 * ch);
        CPA16(su + 36864 + r * 144 + 16 * ch, Vg + (size_t)r * SEQ + 8 * ch);
    }
    CPA_COMMIT();
    // g1: K1 + V1
#pragma unroll
    for (int i = 0; i < 2; i++) {
        int id = t + i * 256;
        int r  = id >> 3;
        int ch = id & 7;
        CPA16(su + 9216 + 9216 + r * 144 + 16 * ch,
              Kg + (size_t)(64 + r) * HEAD + 8 * ch);
        CPA16(su + 36864 + 9216 + r * 144 + 16 * ch,
              Vg + (size_t)r * SEQ + 64 + 8 * ch);
    }
    CPA_COMMIT();

    CPA_WAIT1();
    __syncthreads();
    uint32_t qf[4][4];
#pragma unroll
    for (int ks = 0; ks < 4; ks++) {
        int k0 = 16 * ks;
        qf[ks][0] = *(const uint32_t*)&sQ[(r0) * 72 + k0 + l2];
        qf[ks][1] = *(const uint32_t*)&sQ[(r0 + 8) * 72 + k0 + l2];
        qf[ks][2] = *(const uint32_t*)&sQ[(r0) * 72 + k0 + l2 + 8];
        qf[ks][3] = *(const uint32_t*)&sQ[(r0 + 8) * 72 + k0 + l2 + 8];
    }

    float m0 = -1e30f, m1 = -1e30f;
    float o[9][4];                       // o[8] = l accumulator (ones-column)
#pragma unroll
    for (int n = 0; n < 9; n++)
#pragma unroll
        for (int c = 0; c < 4; c++) o[n][c] = 0.f;

    int st = 0;
    for (int kt = 0; kt <= qt; kt++) {
        CPA_WAIT1();
        __syncthreads();

        const uint32_t suK = su + 9216 + st * 9216 + koff;
        const uint32_t suV = su + 36864 + st * 9216 + voff;
        const __half* sVc = sh + 18432 + st * 4608;  (void)sVc;

        float s[4][4];
#pragma unroll
        for (int n = 0; n < 4; n++)
#pragma unroll
            for (int c = 0; c < 4; c++) s[n][c] = 0.f;

#pragma unroll
        for (int ks = 0; ks < 4; ks++) {
#pragma unroll
            for (int nb = 0; nb < 4; nb += 2) {
                uint32_t b00, b01, b10, b11;
                ldsm_x4(b00, b01, b10, b11, suK + nb * 1152 + 32 * ks);
                mma_f16(s[nb],     qf[ks][0], qf[ks][1], qf[ks][2], qf[ks][3], b00, b01);
                mma_f16(s[nb + 1], qf[ks][0], qf[ks][1], qf[ks][2], qf[ks][3], b10, b11);
            }
        }

        if (kt == qt) {
#pragma unroll
            for (int n = 0; n < 4; n++) {
                int c0 = 32 * g + 8 * n + l2;
                if (c0     > r0    ) s[n][0] = -1e30f;
                if (c0 + 1 > r0    ) s[n][1] = -1e30f;
                if (c0     > r0 + 8) s[n][2] = -1e30f;
                if (c0 + 1 > r0 + 8) s[n][3] = -1e30f;
            }
        }

        float mx0 = fmaxf(fmaxf(s[0][0], s[0][1]), fmaxf(s[1][0], s[1][1]));
        mx0 = fmaxf(mx0, fmaxf(fmaxf(s[2][0], s[2][1]), fmaxf(s[3][0], s[3][1])));
        float mx1 = fmaxf(fmaxf(s[0][2], s[0][3]), fmaxf(s[1][2], s[1][3]));
        mx1 = fmaxf(mx1, fmaxf(fmaxf(s[2][2], s[2][3]), fmaxf(s[3][2], s[3][3])));

        __half2 hmx = __floats2half2_rn(mx0, mx1);
        hmx = __hmax2(hmx, u32_to_h2(__shfl_xor_sync(0xffffffffu, h2_to_u32(hmx), 1)));
        hmx = __hmax2(hmx, u32_to_h2(__shfl_xor_sync(0xffffffffu, h2_to_u32(hmx), 2)));
        float2 fmx = __half22float2(hmx);

        float mn0 = fmaxf(m0, fmx.x);
        float mn1 = fmaxf(m1, fmx.y);
        float alpha0 = ex2(m0 - mn0);
        float alpha1 = ex2(m1 - mn1);
        m0 = mn0; m1 = mn1;

        uint32_t p[8];
#pragma unroll
        for (int n = 0; n < 4; n++) {
            p[2 * n]     = ex2_h2(h2_to_u32(__floats2half2_rn(s[n][0] - mn0, s[n][1] - mn0)));
            p[2 * n + 1] = ex2_h2(h2_to_u32(__floats2half2_rn(s[n][2] - mn1, s[n][3] - mn1)));
        }

#pragma unroll
        for (int n = 0; n < 9; n++) {
            o[n][0] *= alpha0; o[n][1] *= alpha0;
            o[n][2] *= alpha1; o[n][3] *= alpha1;
        }

#pragma unroll
        for (int ks = 0; ks < 2; ks++) {
            uint32_t a0 = p[4 * ks + 0];
            uint32_t a1 = p[4 * ks + 1];
            uint32_t a2 = p[4 * ks + 2];
            uint32_t a3 = p[4 * ks + 3];
#pragma unroll
            for (int nb = 0; nb < 8; nb += 2) {
                uint32_t b00, b01, b10, b11;
                ldsm_x4(b00, b01, b10, b11, suV + nb * 1152 + 64 * g + 32 * ks);
                mma_f16(o[nb],     a0, a1, a2, a3, b00, b01);
                mma_f16(o[nb + 1], a0, a1, a2, a3, b10, b11);
            }
            mma_f16(o[8], a0, a1, a2, a3, ONES_H2, ONES_H2);
        }

        if (kt + 2 <= qt) {
            int ps = st + 2;
            if (ps >= 3) ps -= 3;
#pragma unroll
            for (int i = 0; i < 2; i++) {
                int id = t + i * 256;
                int r  = id >> 3;
                int ch = id & 7;
                CPA16(su + 9216 + ps * 9216 + r * 144 + 16 * ch,
                      Kg + (size_t)((kt + 2) * 64 + r) * HEAD + 8 * ch);
                CPA16(su + 36864 + ps * 9216 + r * 144 + 16 * ch,
                      Vg + (size_t)r * SEQ + (kt + 2) * 64 + 8 * ch);
            }
        }
        CPA_COMMIT();
        if (++st == 3) st = 0;
    }

    CPA_WAIT0();
    __syncthreads();

    const float l0 = o[8][0];
    const float l1 = o[8][2];

    float* sML = (float*)smraw;
    if (l3 == 0) {
        sML[((g * 64 + r0)     << 1) + 0] = m0;
        sML[((g * 64 + r0)     << 1) + 1] = l0;
        sML[((g * 64 + r0 + 8) << 1) + 0] = m1;
        sML[((g * 64 + r0 + 8) << 1) + 1] = l1;
    }
    __syncthreads();
    const int og = 1 - g;
    float mo0 = sML[((og * 64 + r0)     << 1) + 0];
    float lo0 = sML[((og * 64 + r0)     << 1) + 1];
    float mo1 = sML[((og * 64 + r0 + 8) << 1) + 0];
    float lo1 = sML[((og * 64 + r0 + 8) << 1) + 1];

    float M0 = fmaxf(m0, mo0), M1 = fmaxf(m1, mo1);
    float sc0 = ex2(m0 - M0), sc1 = ex2(m1 - M1);
    float L0 = l0 * sc0 + lo0 * ex2(mo0 - M0);
    float L1 = l1 * sc1 + lo1 * ex2(mo1 - M1);

#pragma unroll
    for (int n = 0; n < 8; n++) {
        o[n][0] *= sc0; o[n][1] *= sc0;
        o[n][2] *= sc1; o[n][3] *= sc1;
    }

    float* sOB = (float*)(smraw + 9216);
    if (g == 1) {
#pragma unroll
        for (int n = 0; n < 8; n++) {
            int cb = 8 * n + l2;
            sOB[(r0) * 68 + cb + 0]     = o[n][0];
            sOB[(r0) * 68 + cb + 1]     = o[n][1];
            sOB[(r0 + 8) * 68 + cb + 0] = o[n][2];
            sOB[(r0 + 8) * 68 + cb + 1] = o[n][3];
        }
    }
    __syncthreads();
    if (g == 0) {
        float inv0 = 1.f / L0;
        float inv1 = 1.f / L1;
        size_t orow0 = (size_t)b * SEQ + qt * 64 + r0;
#pragma unroll
        for (int n = 0; n < 8; n++) {
            int cb = 8 * n + l2;
            float2 v0, v1;
            v0.x = (o[n][0] + sOB[(r0) * 68 + cb + 0])     * inv0;
            v0.y = (o[n][1] + sOB[(r0) * 68 + cb + 1])     * inv0;
            v1.x = (o[n][2] + sOB[(r0 + 8) * 68 + cb + 0]) * inv1;
            v1.y = (o[n][3] + sOB[(r0 + 8) * 68 + cb + 1]) * inv1;
            *(float2*)&out[orow0 * HEAD + cb]       = v0;
            *(float2*)&out[(orow0 + 8) * HEAD + cb] = v1;
        }
    }
}

extern "C" void kernel_launch(void* const* d_in, const int* in_sizes, int n_in,
                              void* d_out, int out_size)
{
    const float* x  = (const float*)d_in[0];
    const float* Wq = (const float*)d_in[1];
    const float* bq = (const float*)d_in[2];
    const float* Wk = (const float*)d_in[3];
    const float* bk = (const float*)d_in[4];
    const float* Wv = (const float*)d_in[5];
    const float* bv = (const float*)d_in[6];
    float* out = (float*)d_out;

    wprep_kernel<<<144, 256>>>(Wq, Wk, Wv);

    const size_t QKV_SMEM = 92160;       // bytes
    cudaFuncSetAttribute(qkv_fused_kernel, cudaFuncAttributeMaxDynamicSharedMemorySize,
                         (int)QKV_SMEM);
    qkv_fused_kernel<<<SEQ * BATCH / 128, 256, QKV_SMEM>>>(x, bq, bk, bv);

    const size_t FLASH_SMEM = 64512;     // bytes: Q 9216 + K 3x9216 + Vt 3x9216
    cudaFuncSetAttribute(flash_kernel, cudaFuncAttributeMaxDynamicSharedMemorySize,
                         (int)FLASH_SMEM);
    flash_kernel<<<SEQ / 64 * BATCH, 256, FLASH_SMEM>>>(out);
}